// round 3
// baseline (speedup 1.0000x reference)
#include <cuda_runtime.h>
#include <math.h>

#define NATOM 32768
#define MNBR 12
#define DIM 64
#define FNBR 41
#define ORIG 92
#define TWO_D 128
#define KTOT 169
#define NCRY 512
#define NA 64
#define CNT1F (393216.0f)
#define CNT2F (32768.0f)
#define EPSBN 1e-5f

// ---------------- scratch (device globals; no allocation) ----------------
__device__ float g_x[2][NATOM * DIM];
__device__ float g_zself[NATOM * TWO_D];
__device__ float g_z[NATOM * MNBR * TWO_D];          // 201 MB
__device__ float g_summed[NATOM * DIM];
__device__ float g_G[NCRY * NA * 384];               // 50 MB
__device__ float g_Ws[3 * 32 * 256];                 // self W pair-interleaved [l][t2][col][kk]
__device__ float g_Wn[3 * 54 * 256];                 // nbr W pair-interleaved [l][t2][col][kk]
__device__ float g_emb[46 * 128];                    // [t2][d][kk]
__device__ float g_bil[32 * 768];                    // [t2][j][kk]
__device__ float g_fcaT[DIM * ORIG];                 // [k][c]
__device__ float g_s1[TWO_D], g_ss1[TWO_D], g_s2[DIM], g_ss2[DIM];

__device__ __forceinline__ float softplusf(float v) {
    return v > 20.0f ? v : log1pf(expf(v));
}

// ---- packed f32x2 helpers ----
__device__ __forceinline__ unsigned long long pk2(float x, float y) {
    unsigned long long r;
    asm("mov.b64 %0, {%1, %2};" : "=l"(r) : "f"(x), "f"(y));
    return r;
}
__device__ __forceinline__ void ffma2(unsigned long long& p, unsigned long long a,
                                      unsigned long long b) {
    asm("fma.rn.f32x2 %0, %1, %2, %0;" : "+l"(p) : "l"(a), "l"(b));
}
__device__ __forceinline__ float hadd2(unsigned long long v) {
    float x, y;
    asm("mov.b64 {%0, %1}, %2;" : "=f"(x), "=f"(y) : "l"(v));
    return x + y;
}
__device__ __forceinline__ unsigned long long lds64(const float* p) {
    return *reinterpret_cast<const unsigned long long*>(p);
}

// ---------------- prep: pair-interleaved weight layouts ----------------
__global__ void prep_kernel(const float* __restrict__ conv_W,
                            const float* __restrict__ embed_W,
                            const float* __restrict__ bil_W,
                            const float* __restrict__ fca_W) {
    int idx = blockIdx.x * blockDim.x + threadIdx.x;
    if (idx < 3 * 32 * 256) {                    // g_Ws
        int l = idx / (32 * 256), r = idx % (32 * 256);
        int t2 = r >> 8, j = r & 255, col = j >> 1, kk = j & 1;
        g_Ws[idx] = conv_W[(l * TWO_D + col) * KTOT + 2 * t2 + kk];
        return;
    }
    int i1 = idx - 3 * 32 * 256;
    if (i1 < 3 * 54 * 256) {                     // g_Wn
        int l = i1 / (54 * 256), r = i1 % (54 * 256);
        int t2 = r >> 8, j = r & 255, col = j >> 1, kk = j & 1;
        int k2 = 2 * t2 + kk;
        g_Wn[i1] = (k2 < 105) ? conv_W[(l * TWO_D + col) * KTOT + 64 + k2] : 0.f;
        return;
    }
    int i2 = i1 - 3 * 54 * 256;
    if (i2 < 46 * 128) {                         // g_emb
        int t2 = i2 >> 7, j = i2 & 127, d = j >> 1, kk = j & 1;
        g_emb[i2] = embed_W[d * ORIG + 2 * t2 + kk];
        return;
    }
    int i3 = i2 - 46 * 128;
    if (i3 < 32 * 768) {                         // g_bil
        int t2 = i3 / 768, r = i3 % 768;
        int jj = r >> 1, kk = r & 1;
        int o = jj >> 6, kcol = jj & 63;
        g_bil[i3] = bil_W[(o * DIM + 2 * t2 + kk) * DIM + kcol];
        return;
    }
    int i4 = i3 - 32 * 768;
    if (i4 < DIM * ORIG) {
        int k = i4 / ORIG, c = i4 % ORIG;
        g_fcaT[i4] = fca_W[c * DIM + k];
    }
}

// ---------------- embedding: 64 rows x 64 cols, K=92 (46 pairs) ----------------
__global__ __launch_bounds__(256, 4) void embed_kernel(const float* __restrict__ atom_fea) {
    extern __shared__ float sm[];
    float* Wf = sm;               // [46][128]
    float* Af = sm + 46 * 128;    // [64][92]
    int t = threadIdx.x;
    int rb = blockIdx.x * 64;
    for (int e = t; e < 46 * 128; e += 256) Wf[e] = g_emb[e];
    for (int e = t; e < 64 * ORIG; e += 256) Af[e] = atom_fea[rb * ORIG + e];
    __syncthreads();
    int tx = t & 31, ty = t >> 5;
    unsigned long long P[8][2];
#pragma unroll
    for (int i = 0; i < 8; i++) { P[i][0] = 0ull; P[i][1] = 0ull; }
    const unsigned long long* Wp = (const unsigned long long*)Wf;
    const unsigned long long* Ap = (const unsigned long long*)Af + (ty * 8) * 46;
    for (int t2 = 0; t2 < 46; t2 += 2) {
        ulonglong2 b0 = *(const ulonglong2*)&Wp[t2 * 64 + 2 * tx];
        ulonglong2 b1 = *(const ulonglong2*)&Wp[(t2 + 1) * 64 + 2 * tx];
#pragma unroll
        for (int i = 0; i < 8; i++) {
            ulonglong2 a = *(const ulonglong2*)&Ap[i * 46 + t2];
            ffma2(P[i][0], a.x, b0.x); ffma2(P[i][1], a.x, b0.y);
            ffma2(P[i][0], a.y, b1.x); ffma2(P[i][1], a.y, b1.y);
        }
    }
#pragma unroll
    for (int i = 0; i < 8; i++)
        *(float2*)&g_x[0][(rb + ty * 8 + i) * DIM + 2 * tx] =
            make_float2(hadd2(P[i][0]), hadd2(P[i][1]));
}

// ---------------- per-layer stat zeroing ----------------
__global__ void zero_stats() {
    int t = threadIdx.x;
    if (t < TWO_D) { g_s1[t] = 0.f; g_ss1[t] = 0.f; }
    if (t < DIM)   { g_s2[t] = 0.f; g_ss2[t] = 0.f; }
}

// ---------------- zself: 64 rows x 64 cols, K=64 (32 pairs) ----------------
__global__ __launch_bounds__(256, 4) void zself_kernel(int l, int buf,
                                                       const float* __restrict__ conv_b) {
    extern __shared__ float sm[];
    float* Wf = sm;               // [32][128]
    float* Af = sm + 32 * 128;    // [64][64]
    int t = threadIdx.x;
    int rb = blockIdx.x * 64;
    int colbase = blockIdx.y * 64;
    const float* x = g_x[buf];
    for (int e = t; e < 32 * 128; e += 256)
        Wf[e] = g_Ws[l * 8192 + (e >> 7) * 256 + colbase * 2 + (e & 127)];
    {
        const float4* xs = (const float4*)(x + rb * DIM);
        float4* Ad = (float4*)Af;
        for (int e = t; e < 1024; e += 256) Ad[e] = xs[e];
    }
    __syncthreads();
    int tx = t & 31, ty = t >> 5;
    int c0 = colbase + 2 * tx;
    unsigned long long P[8][2];
    {
        unsigned long long i0 = pk2(conv_b[l * TWO_D + c0], 0.f);
        unsigned long long i1 = pk2(conv_b[l * TWO_D + c0 + 1], 0.f);
#pragma unroll
        for (int i = 0; i < 8; i++) { P[i][0] = i0; P[i][1] = i1; }
    }
    const unsigned long long* Wp = (const unsigned long long*)Wf;
    const unsigned long long* Ap = (const unsigned long long*)Af + (ty * 8) * 32;
    for (int t2 = 0; t2 < 32; t2 += 2) {
        ulonglong2 b0 = *(const ulonglong2*)&Wp[t2 * 64 + 2 * tx];
        ulonglong2 b1 = *(const ulonglong2*)&Wp[(t2 + 1) * 64 + 2 * tx];
#pragma unroll
        for (int i = 0; i < 8; i++) {
            ulonglong2 a = *(const ulonglong2*)&Ap[i * 32 + t2];
            ffma2(P[i][0], a.x, b0.x); ffma2(P[i][1], a.x, b0.y);
            ffma2(P[i][0], a.y, b1.x); ffma2(P[i][1], a.y, b1.y);
        }
    }
#pragma unroll
    for (int i = 0; i < 8; i++)
        *(float2*)&g_zself[(rb + ty * 8 + i) * TWO_D + c0] =
            make_float2(hadd2(P[i][0]), hadd2(P[i][1]));
}

// ---------------- main conv GEMM: 128 rows x 64 cols, K=105 (54 padded pairs) ----------------
__global__ __launch_bounds__(512, 2) void convz_kernel(int l, int buf,
                                                       const float* __restrict__ nbr_fea,
                                                       const int* __restrict__ nbr_idx) {
    extern __shared__ float sm[];
    float* Wf = sm;                // [54][128] = 6912
    float* Af = sm + 54 * 128;     // [128][108] = 13824
    __shared__ int nbr_s[128];
    int t = threadIdx.x;
    int rb = blockIdx.x * 128;
    int colbase = blockIdx.y * 64;
    const float* x = g_x[buf];
    if (t < 128) nbr_s[t] = nbr_idx[rb + t];
    {
        const float* Wg = g_Wn + l * 54 * 256 + colbase * 2;
        for (int e = t; e < 54 * 128; e += 512)
            Wf[e] = Wg[(e >> 7) * 256 + (e & 127)];
    }
    __syncthreads();
    int warp = t >> 5, lane = t & 31;
    for (int m = warp; m < 128; m += 16) {
        float* Ar = Af + m * 108;
        int nbr = nbr_s[m];
        Ar[lane]      = x[nbr * DIM + lane];
        Ar[32 + lane] = x[nbr * DIM + 32 + lane];
        const float* nf = nbr_fea + (long)(rb + m) * FNBR;
        Ar[64 + lane] = nf[lane];
        if (lane < 9) Ar[96 + lane] = nf[32 + lane];
        if (lane < 3) Ar[105 + lane] = 0.f;
    }
    __syncthreads();
    int tx = t & 31, ty = t >> 5;   // ty 0..15
    unsigned long long P[8][2];
#pragma unroll
    for (int i = 0; i < 8; i++) { P[i][0] = 0ull; P[i][1] = 0ull; }
    const unsigned long long* Wp = (const unsigned long long*)Wf;
    const unsigned long long* Ap = (const unsigned long long*)Af + (ty * 8) * 54;
    for (int t2 = 0; t2 < 54; t2 += 2) {
        ulonglong2 b0 = *(const ulonglong2*)&Wp[t2 * 64 + 2 * tx];
        ulonglong2 b1 = *(const ulonglong2*)&Wp[(t2 + 1) * 64 + 2 * tx];
#pragma unroll
        for (int i = 0; i < 8; i++) {
            ulonglong2 a = *(const ulonglong2*)&Ap[i * 54 + t2];
            ffma2(P[i][0], a.x, b0.x); ffma2(P[i][1], a.x, b0.y);
            ffma2(P[i][0], a.y, b1.x); ffma2(P[i][1], a.y, b1.y);
        }
    }
    int c0 = colbase + 2 * tx;
    float s0 = 0.f, s1 = 0.f, q0 = 0.f, q1 = 0.f;
#pragma unroll
    for (int i = 0; i < 8; i++) {
        int row = rb + ty * 8 + i;
        int n = row / MNBR;
        float2 zs = *(const float2*)&g_zself[n * TWO_D + c0];
        float v0 = hadd2(P[i][0]) + zs.x;
        float v1 = hadd2(P[i][1]) + zs.y;
        *(float2*)&g_z[(long)row * TWO_D + c0] = make_float2(v0, v1);
        s0 += v0; q0 += v0 * v0;
        s1 += v1; q1 += v1 * v1;
    }
    __syncthreads();
    float* redS = Af;
    float* redQ = Af + 1024;
    redS[ty * 64 + 2 * tx] = s0; redS[ty * 64 + 2 * tx + 1] = s1;
    redQ[ty * 64 + 2 * tx] = q0; redQ[ty * 64 + 2 * tx + 1] = q1;
    __syncthreads();
    if (t < 64) {
        float tot = 0.f;
#pragma unroll
        for (int w = 0; w < 16; w++) tot += redS[w * 64 + t];
        atomicAdd(&g_s1[colbase + t], tot);
    } else if (t < 128) {
        int o = t - 64;
        float tot = 0.f;
#pragma unroll
        for (int w = 0; w < 16; w++) tot += redQ[w * 64 + o];
        atomicAdd(&g_ss1[colbase + o], tot);
    }
}

// ---------------- BN1 + gate + sum over neighbors, BN2 stats (float2) ----------------
__global__ __launch_bounds__(256) void reduce_kernel(int l,
                                                     const float* __restrict__ bn1_g,
                                                     const float* __restrict__ bn1_b) {
    int c = threadIdx.x & 31, grp = threadIdx.x >> 5;
    int d0 = 2 * c;
    float inv = 1.0f / CNT1F;
    float mf0 = g_s1[d0] * inv, mf1 = g_s1[d0 + 1] * inv;
    float vf0 = g_ss1[d0] * inv - mf0 * mf0, vf1 = g_ss1[d0 + 1] * inv - mf1 * mf1;
    float scf0 = rsqrtf(vf0 + EPSBN) * bn1_g[l * TWO_D + d0];
    float scf1 = rsqrtf(vf1 + EPSBN) * bn1_g[l * TWO_D + d0 + 1];
    float shf0 = bn1_b[l * TWO_D + d0] - mf0 * scf0;
    float shf1 = bn1_b[l * TWO_D + d0 + 1] - mf1 * scf1;
    float mc0 = g_s1[64 + d0] * inv, mc1 = g_s1[64 + d0 + 1] * inv;
    float vc0 = g_ss1[64 + d0] * inv - mc0 * mc0, vc1 = g_ss1[64 + d0 + 1] * inv - mc1 * mc1;
    float scc0 = rsqrtf(vc0 + EPSBN) * bn1_g[l * TWO_D + 64 + d0];
    float scc1 = rsqrtf(vc1 + EPSBN) * bn1_g[l * TWO_D + 64 + d0 + 1];
    float shc0 = bn1_b[l * TWO_D + 64 + d0] - mc0 * scc0;
    float shc1 = bn1_b[l * TWO_D + 64 + d0 + 1] - mc1 * scc1;

    float ls0 = 0.f, ls1 = 0.f, lq0 = 0.f, lq1 = 0.f;
    int n0 = blockIdx.x * 16 + grp * 2;
    for (int a = 0; a < 2; a++) {
        int n = n0 + a;
        const float* zr = g_z + (long)n * MNBR * TWO_D;
        float a0 = 0.f, a1 = 0.f;
#pragma unroll
        for (int m = 0; m < MNBR; m++) {
            float2 zf = *(const float2*)&zr[m * TWO_D + d0];
            float2 zc = *(const float2*)&zr[m * TWO_D + 64 + d0];
            float f0 = zf.x * scf0 + shf0, f1 = zf.y * scf1 + shf1;
            float c0v = zc.x * scc0 + shc0, c1v = zc.y * scc1 + shc1;
            a0 += softplusf(c0v) / (1.0f + expf(-f0));
            a1 += softplusf(c1v) / (1.0f + expf(-f1));
        }
        *(float2*)&g_summed[n * DIM + d0] = make_float2(a0, a1);
        ls0 += a0; lq0 += a0 * a0;
        ls1 += a1; lq1 += a1 * a1;
    }
    atomicAdd(&g_s2[d0], ls0);
    atomicAdd(&g_s2[d0 + 1], ls1);
    atomicAdd(&g_ss2[d0], lq0);
    atomicAdd(&g_ss2[d0 + 1], lq1);
}

// ---------------- BN2 + residual softplus -> x_out ----------------
__global__ __launch_bounds__(256) void bnres_kernel(int l, int buf,
                                                    const float* __restrict__ bn2_g,
                                                    const float* __restrict__ bn2_b) {
    int gid = blockIdx.x * 256 + threadIdx.x;
    int d = gid & 63;
    float inv = 1.0f / CNT2F;
    float m2 = g_s2[d] * inv;
    float v2 = g_ss2[d] * inv - m2 * m2;
    float sc = rsqrtf(v2 + EPSBN) * bn2_g[l * DIM + d];
    float sh = bn2_b[l * DIM + d] - m2 * sc;
    float v = g_x[buf][gid] + g_summed[gid] * sc + sh;
    g_x[1 - buf][gid] = softplusf(v);
}

// ---------------- G: 64 rows x 64 cols of 384, K=64 (32 pairs) ----------------
__global__ __launch_bounds__(256, 4) void gmat_kernel(int buf, const int* __restrict__ cidx) {
    extern __shared__ float sm[];
    float* Wf = sm;               // [32][128]
    float* Af = sm + 32 * 128;    // [64][64]
    __shared__ int cid_s[64];
    int t = threadIdx.x;
    int rb = blockIdx.x * 64;
    int jbase = blockIdx.y * 64;
    const float* x = g_x[buf];
    if (t < 64) cid_s[t] = cidx[rb + t];
    for (int e = t; e < 32 * 128; e += 256)
        Wf[e] = g_bil[(e >> 7) * 768 + jbase * 2 + (e & 127)];
    __syncthreads();
    int warp = t >> 5, lane = t & 31;
    for (int m = warp; m < 64; m += 8) {
        int a = cid_s[m];
        Af[m * 64 + lane]      = x[a * DIM + lane];
        Af[m * 64 + 32 + lane] = x[a * DIM + 32 + lane];
    }
    __syncthreads();
    int tx = t & 31, ty = t >> 5;
    unsigned long long P[8][2];
#pragma unroll
    for (int i = 0; i < 8; i++) { P[i][0] = 0ull; P[i][1] = 0ull; }
    const unsigned long long* Wp = (const unsigned long long*)Wf;
    const unsigned long long* Ap = (const unsigned long long*)Af + (ty * 8) * 32;
    for (int t2 = 0; t2 < 32; t2 += 2) {
        ulonglong2 b0 = *(const ulonglong2*)&Wp[t2 * 64 + 2 * tx];
        ulonglong2 b1 = *(const ulonglong2*)&Wp[(t2 + 1) * 64 + 2 * tx];
#pragma unroll
        for (int i = 0; i < 8; i++) {
            ulonglong2 a = *(const ulonglong2*)&Ap[i * 32 + t2];
            ffma2(P[i][0], a.x, b0.x); ffma2(P[i][1], a.x, b0.y);
            ffma2(P[i][0], a.y, b1.x); ffma2(P[i][1], a.y, b1.y);
        }
    }
#pragma unroll
    for (int i = 0; i < 8; i++)
        *(float2*)&g_G[(long)(rb + ty * 8 + i) * 384 + jbase + 2 * tx] =
            make_float2(hadd2(P[i][0]), hadd2(P[i][1]));
}

// ---------------- edge: 8 i-rows x 64 j per block ----------------
__global__ __launch_bounds__(256) void edge_kernel(int buf, const int* __restrict__ cidx,
                                                   const float* __restrict__ bil_b,
                                                   const float* __restrict__ fc1_W,
                                                   const float* __restrict__ fc1_b,
                                                   float* __restrict__ out) {
    __shared__ unsigned long long Gp[8 * 32 * 6];   // [i][t2][o]
    __shared__ float f_s[64 * 66];                  // [j][k], stride 66
    __shared__ int cid_s[64];
    __shared__ float s_fc1W[36], s_fc1b[6], s_bilb[6];
    int b = blockIdx.x, ib = blockIdx.y, t = threadIdx.x;
    const float* x = g_x[buf];
    if (t < 64) cid_s[t] = cidx[b * 64 + t];
    if (t < 36) s_fc1W[t] = fc1_W[t];
    if (t >= 64 && t < 70) s_fc1b[t - 64] = fc1_b[t - 64];
    if (t >= 96 && t < 102) s_bilb[t - 96] = bil_b[t - 96];
    __syncthreads();
    for (int e = t; e < 4096; e += 256) {
        int j = e >> 6, k = e & 63;
        f_s[j * 66 + k] = x[cid_s[j] * DIM + k];
    }
    {
        float* Gpf = (float*)Gp;
        const float* Gsrc = g_G + (long)(b * 64 + ib * 8) * 384;
        for (int e = t; e < 3072; e += 256) {
            int i = e / 384, r = e % 384;
            int o = r >> 6, k = r & 63;
            Gpf[((i * 32 + (k >> 1)) * 6 + o) * 2 + (k & 1)] = Gsrc[i * 384 + r];
        }
    }
    __syncthreads();
    int w = t >> 5, lane = t & 31;
    const float* f0 = f_s + (2 * lane) * 66;
    const float* f1 = f_s + (2 * lane + 1) * 66;
    const unsigned long long* Gi = Gp + w * 192;
    unsigned long long acc[2][6];
#pragma unroll
    for (int o = 0; o < 6; o++) {
        unsigned long long bi = pk2(s_bilb[o], 0.f);
        acc[0][o] = bi; acc[1][o] = bi;
    }
#pragma unroll 4
    for (int t2 = 0; t2 < 32; t2++) {
        ulonglong2 g01 = *(const ulonglong2*)&Gi[t2 * 6];
        ulonglong2 g23 = *(const ulonglong2*)&Gi[t2 * 6 + 2];
        ulonglong2 g45 = *(const ulonglong2*)&Gi[t2 * 6 + 4];
        unsigned long long a0 = lds64(f0 + 2 * t2);
        unsigned long long a1 = lds64(f1 + 2 * t2);
        ffma2(acc[0][0], a0, g01.x); ffma2(acc[0][1], a0, g01.y);
        ffma2(acc[0][2], a0, g23.x); ffma2(acc[0][3], a0, g23.y);
        ffma2(acc[0][4], a0, g45.x); ffma2(acc[0][5], a0, g45.y);
        ffma2(acc[1][0], a1, g01.x); ffma2(acc[1][1], a1, g01.y);
        ffma2(acc[1][2], a1, g23.x); ffma2(acc[1][3], a1, g23.y);
        ffma2(acc[1][4], a1, g45.x); ffma2(acc[1][5], a1, g45.y);
    }
    float r12[12];
#pragma unroll
    for (int jj = 0; jj < 2; jj++) {
        float ev[6], tr[6];
#pragma unroll
        for (int o = 0; o < 6; o++) ev[o] = hadd2(acc[jj][o]);
#pragma unroll
        for (int r = 0; r < 6; r++) {
            float a = s_fc1b[r];
#pragma unroll
            for (int o = 0; o < 6; o++) a = fmaf(s_fc1W[r * 6 + o], ev[o], a);
            tr[r] = a;
        }
        float mx = tr[0];
#pragma unroll
        for (int r = 1; r < 6; r++) mx = fmaxf(mx, tr[r]);
        float se = 0.f;
#pragma unroll
        for (int r = 0; r < 6; r++) se += expf(tr[r] - mx);
        float lse = mx + logf(se);
#pragma unroll
        for (int r = 0; r < 6; r++) r12[jj * 6 + r] = tr[r] - lse;
    }
    float* op = out + ((long)b * 4096 + (ib * 8 + w) * 64 + 2 * lane) * 6;
    *(float4*)&op[0] = make_float4(r12[0], r12[1], r12[2], r12[3]);
    *(float4*)&op[4] = make_float4(r12[4], r12[5], r12[6], r12[7]);
    *(float4*)&op[8] = make_float4(r12[8], r12[9], r12[10], r12[11]);
}

// ---------------- atom_out = f @ fca_W^T + fca_b ----------------
__global__ __launch_bounds__(96) void atomout_kernel(int buf, const int* __restrict__ cidx,
                                                     const float* __restrict__ fca_b,
                                                     float* __restrict__ out2) {
    __shared__ float xr[64];
    int t = threadIdx.x;
    int r = blockIdx.x;
    int atom = cidx[r];
    if (t < 64) xr[t] = g_x[buf][atom * DIM + t];
    __syncthreads();
    if (t < ORIG) {
        float a = fca_b[t];
#pragma unroll 16
        for (int k = 0; k < 64; k++) a = fmaf(xr[k], g_fcaT[k * ORIG + t], a);
        out2[(long)r * ORIG + t] = a;
    }
}

// ---------------- launch ----------------
#define CONVZ_SM ((54 * 128 + 128 * 108) * 4)
#define ZS_SM ((32 * 128 + 64 * 64) * 4)
#define EMB_SM ((46 * 128 + 64 * ORIG) * 4)

extern "C" void kernel_launch(void* const* d_in, const int* in_sizes, int n_in,
                              void* d_out, int out_size) {
    (void)in_sizes; (void)n_in; (void)out_size;
    const float* atom_fea = (const float*)d_in[0];
    const float* nbr_fea  = (const float*)d_in[1];
    const int*   nbr_idx  = (const int*)d_in[2];
    const int*   cidx     = (const int*)d_in[3];
    const float* embed_W  = (const float*)d_in[4];
    const float* conv_W   = (const float*)d_in[5];
    const float* conv_b   = (const float*)d_in[6];
    const float* bn1_g    = (const float*)d_in[7];
    const float* bn1_b    = (const float*)d_in[8];
    const float* bn2_g    = (const float*)d_in[9];
    const float* bn2_b    = (const float*)d_in[10];
    const float* bil_W    = (const float*)d_in[11];
    const float* bil_b    = (const float*)d_in[12];
    const float* fc1_W    = (const float*)d_in[13];
    const float* fc1_b    = (const float*)d_in[14];
    const float* fca_W    = (const float*)d_in[15];
    const float* fca_b    = (const float*)d_in[16];
    float* out = (float*)d_out;

    cudaFuncSetAttribute(convz_kernel, cudaFuncAttributeMaxDynamicSharedMemorySize, CONVZ_SM);

    int prep_elems = 3 * 32 * 256 + 3 * 54 * 256 + 46 * 128 + 32 * 768 + DIM * ORIG;
    prep_kernel<<<(prep_elems + 255) / 256, 256>>>(conv_W, embed_W, bil_W, fca_W);
    embed_kernel<<<NATOM / 64, 256, EMB_SM>>>(atom_fea);

    int buf = 0;
    for (int l = 0; l < 3; l++) {
        zero_stats<<<1, 128>>>();
        zself_kernel<<<dim3(NATOM / 64, 2), 256, ZS_SM>>>(l, buf, conv_b);
        convz_kernel<<<dim3(NATOM * MNBR / 128, 2), 512, CONVZ_SM>>>(l, buf, nbr_fea, nbr_idx);
        reduce_kernel<<<NATOM / 16, 256>>>(l, bn1_g, bn1_b);
        bnres_kernel<<<(NATOM * DIM) / 256, 256>>>(l, buf, bn2_g, bn2_b);
        buf = 1 - buf;
    }

    gmat_kernel<<<dim3(NCRY * NA / 64, 6), 256, ZS_SM>>>(buf, cidx);
    edge_kernel<<<dim3(NCRY, 8), 256>>>(buf, cidx, bil_b, fc1_W, fc1_b, out);
    atomout_kernel<<<NCRY * NA, 96>>>(buf, cidx, fca_b, out + (long)NCRY * NA * NA * 6);
}